// round 12
// baseline (speedup 1.0000x reference)
#include <cuda_runtime.h>
#include <cuda_fp16.h>
#include <math.h>

#define NE 3200000
#define NN 100000
#define EPT 4
#define SCAN_T 512
#define SCAN_NB 196   // 196*512 = 100352 >= NN

// ---------------- device state ----------------
__device__ float g_W1[16*5];
__device__ float g_b1[16];
__device__ float g_W2[32*16];
__device__ float g_b2[32];
__device__ float g_W3[16*35];
__device__ float g_b3[16];
__device__ float g_W4[16];
__device__ float g_b4[1];

__device__ int4   g_sedge[NE];      // dst-sorted {src, dst, ea.x bits, ea.y bits}
__device__ int    g_cnt[NN];        // static zero-init; re-zeroed by scan_blocks each replay
__device__ int    g_off[NN];
__device__ int    g_pos[NN];
__device__ int    g_bsum[SCAN_NB];
__device__ int    g_bpre[SCAN_NB];

__device__ float4   g_xp[NN];       // (x0, x1, x2, unused)
__device__ unsigned g_agg[NN * 32]; // fp32 bit patterns, all values >= 0
__device__ int      g_is_i32;       // monotonic, input-determined; set by prep_init blocks

__device__ __forceinline__ float softplusf(float v) {
    return (v > 20.f) ? v : log1pf(expf(v));
}

__device__ __forceinline__ unsigned hmax2_bits(unsigned a, unsigned b) {
    __half2 ha = *reinterpret_cast<__half2*>(&a);
    __half2 hb = *reinterpret_cast<__half2*>(&b);
    __half2 r = __hmax2(ha, hb);
    return *reinterpret_cast<unsigned*>(&r);
}

// ---------------- mega-prep: detect + zero agg + pack x + weights + histogram ----------------
// grid must be 3125 x 256 (covers 800000 uint4 of agg and 3.2M hist edges at 4/thread)
__global__ void __launch_bounds__(256) prep_init(
    const float* __restrict__ x, const int* __restrict__ ei,
    const float* w1m, const float* w1r, const float* b1m, const float* b1r, const float* e1w, const float* e1b,
    const float* w2m, const float* w2r, const float* b2m, const float* b2r, const float* e2w, const float* e2b,
    const float* w3m, const float* w3r, const float* b3m, const float* b3r, const float* e3w, const float* e3b,
    const float* w4m, const float* w4r, const float* b4m, const float* b4r, const float* e4w, const float* e4b)
{
    __shared__ int s_i32;
    if (threadIdx.x == 0) s_i32 = 0;
    __syncthreads();

    int i = blockIdx.x * blockDim.x + threadIdx.x;
    int stride = gridDim.x * blockDim.x;

    // block-local layout detection over this block's 1024 edge records:
    // int64 layout -> odd 32-bit words are high words of values < NN -> all zero.
    int ebase = blockIdx.x * 1024 + threadIdx.x;
    unsigned w_or = 0;
    #pragma unroll
    for (int k = 0; k < 4; k++)
        w_or |= ((const unsigned*)ei)[2 * (ebase + k * 256) + 1];
    if (w_or) s_i32 = 1;            // benign race

    // zero agg (exact cover)
    reinterpret_cast<uint4*>(g_agg)[i] = make_uint4(0u, 0u, 0u, 0u);

    // pack x
    if (i < NN) g_xp[i] = make_float4(x[3*i + 0], x[3*i + 1], x[3*i + 2], 0.f);

    // sample weights
    for (int t = i; t < 16*5;  t += stride) g_W1[t] = w1m[t] + softplusf(w1r[t]) * e1w[t];
    for (int t = i; t < 16;    t += stride) g_b1[t] = b1m[t] + softplusf(b1r[t]) * e1b[t];
    for (int t = i; t < 32*16; t += stride) g_W2[t] = w2m[t] + softplusf(w2r[t]) * e2w[t];
    for (int t = i; t < 32;    t += stride) g_b2[t] = b2m[t] + softplusf(b2r[t]) * e2b[t];
    for (int t = i; t < 16*35; t += stride) g_W3[t] = w3m[t] + softplusf(w3r[t]) * e3w[t];
    for (int t = i; t < 16;    t += stride) g_b3[t] = b3m[t] + softplusf(b3r[t]) * e3b[t];
    for (int t = i; t < 16;    t += stride) g_W4[t] = w4m[t] + softplusf(w4r[t]) * e4w[t];
    for (int t = i; t < 1;     t += stride) g_b4[t] = b4m[t] + softplusf(b4r[t]) * e4b[t];

    __syncthreads();
    bool is32 = (s_i32 != 0);
    if (threadIdx.x == 0 && is32) atomicExch(&g_is_i32, 1);  // publish for scatter

    // histogram: 4 edges/thread (g_cnt zeroed by prior replay's scan_blocks / static init)
    #pragma unroll
    for (int k = 0; k < 4; k++) {
        int e = ebase + k * 256;
        int d = is32 ? ei[NE + e] : ei[2*(NE + e)];
        if ((unsigned)d >= NN) d = 0;
        atomicAdd(&g_cnt[d], 1);
    }
}

// ---------------- helpers to read edge index in either width ----------------
__device__ __forceinline__ int load_src(const int* ei, int e) {
    int s = g_is_i32 ? ei[e] : ei[2*e];
    return ((unsigned)s >= NN) ? 0 : s;
}
__device__ __forceinline__ int load_dst(const int* ei, int e) {
    int d = g_is_i32 ? ei[NE + e] : ei[2*(NE + e)];
    return ((unsigned)d >= NN) ? 0 : d;
}

// ---------------- scan (re-zeros cnt for the next replay) ----------------
__global__ void scan_blocks()
{
    __shared__ int s[SCAN_T];
    int t = threadIdx.x;
    int i = blockIdx.x * SCAN_T + t;
    int v = (i < NN) ? g_cnt[i] : 0;
    if (i < NN) g_cnt[i] = 0;       // re-zero for next replay (deterministic)
    s[t] = v;
    __syncthreads();
    for (int off = 1; off < SCAN_T; off <<= 1) {
        int x = (t >= off) ? s[t - off] : 0;
        __syncthreads();
        s[t] += x;
        __syncthreads();
    }
    if (i < NN) g_off[i] = s[t] - v;
    if (t == SCAN_T - 1) g_bsum[blockIdx.x] = s[t];
}

__global__ void scan_sums()
{
    __shared__ int s[256];
    int t = threadIdx.x;
    int v = (t < SCAN_NB) ? g_bsum[t] : 0;
    s[t] = v;
    __syncthreads();
    for (int off = 1; off < 256; off <<= 1) {
        int x = (t >= off) ? s[t - off] : 0;
        __syncthreads();
        s[t] += x;
        __syncthreads();
    }
    if (t < SCAN_NB) g_bpre[t] = s[t] - v;
}

__global__ void scan_fixup()
{
    int i = blockIdx.x * blockDim.x + threadIdx.x;
    if (i < NN) g_pos[i] = g_off[i] + g_bpre[i / SCAN_T];
}

// ---------------- scatter ----------------
__global__ void scatter_kernel(const int* __restrict__ ei, const float2* __restrict__ ea)
{
    int e = blockIdx.x * blockDim.x + threadIdx.x;
    if (e >= NE) return;
    int d = load_dst(ei, e);
    int p = atomicAdd(&g_pos[d], 1);
    float2 a = ea[e];
    g_sedge[p] = make_int4(load_src(ei, e), d, __float_as_int(a.x), __float_as_int(a.y));
}

// ---------------- fused edge MLP (fp16, strided EPT=4, two output phases) ----------------
__global__ void __launch_bounds__(256) edge_fused_kernel()
{
    __shared__ unsigned sW1h[5*8];     // half2(W1[2j][i], W1[2j+1][i]) at [i*8+jp]
    __shared__ unsigned sb1h[8];
    __shared__ unsigned sW2h[16*16];   // half2(W2[2jp][k], W2[2jp+1][k]) at [k*16+jp]
    __shared__ unsigned sb2h[16];

    for (int i = threadIdx.x; i < 40; i += blockDim.x) {
        int in = i >> 3, jp = i & 7;
        __half2 h = __floats2half2_rn(g_W1[(2*jp)*5 + in], g_W1[(2*jp+1)*5 + in]);
        sW1h[i] = *reinterpret_cast<unsigned*>(&h);
    }
    for (int i = threadIdx.x; i < 8; i += blockDim.x) {
        __half2 h = __floats2half2_rn(g_b1[2*i], g_b1[2*i+1]);
        sb1h[i] = *reinterpret_cast<unsigned*>(&h);
    }
    for (int i = threadIdx.x; i < 256; i += blockDim.x) {
        int k = i >> 4, jp = i & 15;
        __half2 h = __floats2half2_rn(g_W2[(2*jp)*16 + k], g_W2[(2*jp+1)*16 + k]);
        sW2h[i] = *reinterpret_cast<unsigned*>(&h);
    }
    for (int i = threadIdx.x; i < 16; i += blockDim.x) {
        __half2 h = __floats2half2_rn(g_b2[2*i], g_b2[2*i+1]);
        sb2h[i] = *reinterpret_cast<unsigned*>(&h);
    }
    __syncthreads();

    const unsigned FULL = 0xffffffffu;
    int lane = threadIdx.x & 31;
    int block_base = blockIdx.x * blockDim.x * EPT;

    // load 4 strided edges (warp holds 32 consecutive sorted edges per window)
    int dst[EPT];
    unsigned m1[EPT][8];

    #pragma unroll
    for (int i = 0; i < EPT; i++) {
        int4 rec = g_sedge[block_base + i * 256 + threadIdx.x];
        dst[i] = rec.y;
        float4 xv = g_xp[rec.x];

        __half2 i0 = __half2half2(__float2half(xv.x));
        __half2 i1 = __half2half2(__float2half(xv.y));
        __half2 i2 = __half2half2(__float2half(xv.z));
        __half2 i3 = __half2half2(__float2half(__int_as_float(rec.z)));
        __half2 i4 = __half2half2(__float2half(__int_as_float(rec.w)));

        #pragma unroll
        for (int jp = 0; jp < 8; jp++) {
            __half2 a = *reinterpret_cast<__half2*>(&sb1h[jp]);
            a = __hfma2(*reinterpret_cast<__half2*>(&sW1h[0*8 + jp]), i0, a);
            a = __hfma2(*reinterpret_cast<__half2*>(&sW1h[1*8 + jp]), i1, a);
            a = __hfma2(*reinterpret_cast<__half2*>(&sW1h[2*8 + jp]), i2, a);
            a = __hfma2(*reinterpret_cast<__half2*>(&sW1h[3*8 + jp]), i3, a);
            a = __hfma2(*reinterpret_cast<__half2*>(&sW1h[4*8 + jp]), i4, a);
            m1[i][jp] = hmax2_bits(*reinterpret_cast<unsigned*>(&a), 0u);
        }
    }

    // two phases over output halves: jp 0..7 (agg cols 0..15), jp 8..15 (cols 16..31)
    #pragma unroll
    for (int ph = 0; ph < 2; ph++) {
        unsigned acc[EPT][8];
        #pragma unroll
        for (int i = 0; i < EPT; i++)
            #pragma unroll
            for (int jp = 0; jp < 8; jp++) acc[i][jp] = sb2h[ph*8 + jp];

        #pragma unroll
        for (int kp = 0; kp < 8; kp++) {
            __half2 lo[EPT], hi[EPT];
            #pragma unroll
            for (int i = 0; i < EPT; i++) {
                __half2 mk = *reinterpret_cast<__half2*>(&m1[i][kp]);
                lo[i] = __low2half2(mk);
                hi[i] = __high2half2(mk);
            }
            #pragma unroll
            for (int jp = 0; jp < 8; jp++) {
                __half2 w0 = *reinterpret_cast<__half2*>(&sW2h[(2*kp)*16   + ph*8 + jp]);
                __half2 w1 = *reinterpret_cast<__half2*>(&sW2h[(2*kp+1)*16 + ph*8 + jp]);
                #pragma unroll
                for (int i = 0; i < EPT; i++) {
                    __half2 a = *reinterpret_cast<__half2*>(&acc[i][jp]);
                    a = __hfma2(w0, lo[i], a);
                    a = __hfma2(w1, hi[i], a);
                    acc[i][jp] = *reinterpret_cast<unsigned*>(&a);
                }
            }
        }
        #pragma unroll
        for (int i = 0; i < EPT; i++)
            #pragma unroll
            for (int jp = 0; jp < 8; jp++) acc[i][jp] = hmax2_bits(acc[i][jp], 0u);

        // per-window segmented suffix max + head flush
        #pragma unroll
        for (int i = 0; i < EPT; i++) {
            int key = dst[i];
            #pragma unroll
            for (int s2 = 1; s2 < 32; s2 <<= 1) {
                int kn = __shfl_down_sync(FULL, key, s2);
                bool take = (lane + s2 < 32) && (kn == key);
                #pragma unroll
                for (int q = 0; q < 8; q++) {
                    unsigned o = __shfl_down_sync(FULL, acc[i][q], s2);
                    if (take) acc[i][q] = hmax2_bits(acc[i][q], o);
                }
            }
            int prev = __shfl_up_sync(FULL, key, 1);
            bool head = (lane == 0) || (prev != key);
            if (head) {
                unsigned* basep = &g_agg[(unsigned)key * 32u + ph * 16];
                #pragma unroll
                for (int q = 0; q < 8; q++) {
                    float2 f = __half22float2(*reinterpret_cast<__half2*>(&acc[i][q]));
                    unsigned b0 = __float_as_uint(f.x);
                    unsigned b1 = __float_as_uint(f.y);
                    if (b0) atomicMax(&basep[2*q],     b0);
                    if (b1) atomicMax(&basep[2*q + 1], b1);
                }
            }
        }
    }
}

// ---------------- node MLP (re-zeros agg in-place for next iteration) ----------------
__global__ void __launch_bounds__(256) node_kernel(float* __restrict__ out, int last)
{
    __shared__ float sW3[16*35], sb3[16], sW4[16], sb4[1];
    for (int i = threadIdx.x; i < 16*35; i += blockDim.x) sW3[i] = g_W3[i];
    for (int i = threadIdx.x; i < 16;    i += blockDim.x) sb3[i] = g_b3[i];
    for (int i = threadIdx.x; i < 16;    i += blockDim.x) sW4[i] = g_W4[i];
    if (threadIdx.x == 0) sb4[0] = g_b4[0];
    __syncthreads();

    int i = blockIdx.x * blockDim.x + threadIdx.x;
    if (i >= NN) return;

    float4 xv = g_xp[i];
    float h[35];
    h[0] = xv.x; h[1] = xv.y; h[2] = xv.z;

    uint4* ar = reinterpret_cast<uint4*>(&g_agg[(size_t)i * 32]);
    #pragma unroll
    for (int q = 0; q < 8; q++) {
        uint4 v = ar[q];
        h[3 + 4*q + 0] = __uint_as_float(v.x);
        h[3 + 4*q + 1] = __uint_as_float(v.y);
        h[3 + 4*q + 2] = __uint_as_float(v.z);
        h[3 + 4*q + 3] = __uint_as_float(v.w);
    }
    // re-zero agg while lines are hot
    #pragma unroll
    for (int q = 0; q < 8; q++) ar[q] = make_uint4(0u, 0u, 0u, 0u);

    float t[16];
    #pragma unroll
    for (int j = 0; j < 16; j++) {
        float s = sb3[j];
        #pragma unroll
        for (int k = 0; k < 35; k++) s = fmaf(sW3[j*35 + k], h[k], s);
        t[j] = fmaxf(s, 0.f);
    }

    float z = sb4[0];
    #pragma unroll
    for (int k = 0; k < 16; k++) z = fmaf(sW4[k], t[k], z);

    float comb = 1.f / (1.f + expf(-z));
    reinterpret_cast<float*>(&g_xp[i])[2] = comb;

    if (last) {
        out[3*i + 0] = xv.x;
        out[3*i + 1] = xv.y;
        out[3*i + 2] = comb;
    }
}

// ---------------- launch ----------------
extern "C" void kernel_launch(void* const* d_in, const int* in_sizes, int n_in,
                              void* d_out, int out_size)
{
    const float* x  = (const float*)d_in[0];
    const float* ea = (const float*)d_in[1];
    const void*  ei = d_in[2];
    const float* P[24];
    for (int i = 0; i < 24; i++) P[i] = (const float*)d_in[3 + i];

    // launch #0: everything that only needs inputs
    prep_init<<<3125, 256>>>(x, (const int*)ei,
        P[0],  P[1],  P[2],  P[3],  P[4],  P[5],
        P[6],  P[7],  P[8],  P[9],  P[10], P[11],
        P[12], P[13], P[14], P[15], P[16], P[17],
        P[18], P[19], P[20], P[21], P[22], P[23]);

    scan_blocks<<<SCAN_NB, SCAN_T>>>();                              // #1
    scan_sums<<<1, 256>>>();                                         // #2
    scan_fixup<<<(NN + 255) / 256, 256>>>();                         // #3
    scatter_kernel<<<(NE + 255) / 256, 256>>>((const int*)ei, (const float2*)ea);  // #4

    const int edge_blocks = NE / (256 * EPT);       // 3125
    const int node_blocks = (NN + 255) / 256;       // 391

    for (int it = 0; it < 3; it++) {
        edge_fused_kernel<<<edge_blocks, 256>>>();                   // #5 (ncu -s 5 lands here)
        node_kernel<<<node_blocks, 256>>>((float*)d_out, it == 2 ? 1 : 0);
    }
}

// round 13
// speedup vs baseline: 1.0231x; 1.0231x over previous
#include <cuda_runtime.h>
#include <cuda_fp16.h>
#include <math.h>

#define NE 3200000
#define NN 100000
#define EPT 4
#define EBLK 128   // edge kernel block size (occupancy: 5 blocks/SM vs 2 at 256)
#define SCAN_T 512
#define SCAN_NB 196   // 196*512 = 100352 >= NN

// ---------------- device state ----------------
__device__ float g_W1[16*5];
__device__ float g_b1[16];
__device__ float g_W2[32*16];
__device__ float g_b2[32];
__device__ float g_W3[16*35];
__device__ float g_b3[16];
__device__ float g_W4[16];
__device__ float g_b4[1];

__device__ int4   g_sedge[NE];      // dst-sorted {src, dst, ea half2 bits, unused}
__device__ int    g_cnt[NN];
__device__ int    g_off[NN];
__device__ int    g_pos[NN];
__device__ int    g_bsum[SCAN_NB];
__device__ int    g_bpre[SCAN_NB];

__device__ float4   g_xp[NN];       // (x0, x1, x2, unused)
__device__ unsigned g_agg[NN * 32]; // fp32 bit patterns, all values >= 0
__device__ int      g_is_i32;

__device__ __forceinline__ float softplusf(float v) {
    return (v > 20.f) ? v : log1pf(expf(v));
}

__device__ __forceinline__ unsigned hmax2_bits(unsigned a, unsigned b) {
    __half2 ha = *reinterpret_cast<__half2*>(&a);
    __half2 hb = *reinterpret_cast<__half2*>(&b);
    __half2 r = __hmax2(ha, hb);
    return *reinterpret_cast<unsigned*>(&r);
}

// ---------------- zero cnt + reset detect flag ----------------
__global__ void zero_cnt()
{
    int i = blockIdx.x * blockDim.x + threadIdx.x;
    if (i < NN) g_cnt[i] = 0;
    if (i == 0) g_is_i32 = 0;
}

__global__ void detect_layout(const unsigned* __restrict__ ei_words)
{
    int t = blockIdx.x * blockDim.x + threadIdx.x;   // 512 samples
    if (ei_words[2*t + 1] != 0u) atomicExch(&g_is_i32, 1);
}

__global__ void zero_agg()
{
    int i = blockIdx.x * blockDim.x + threadIdx.x;   // NN*32/4 uint4s
    uint4* p = reinterpret_cast<uint4*>(g_agg);
    if (i < (NN * 32) / 4) p[i] = make_uint4(0u, 0u, 0u, 0u);
}

// ---------------- prep: sample Bayesian weights ----------------
__global__ void prep_weights(
    const float* w1m, const float* w1r, const float* b1m, const float* b1r, const float* e1w, const float* e1b,
    const float* w2m, const float* w2r, const float* b2m, const float* b2r, const float* e2w, const float* e2b,
    const float* w3m, const float* w3r, const float* b3m, const float* b3r, const float* e3w, const float* e3b,
    const float* w4m, const float* w4r, const float* b4m, const float* b4r, const float* e4w, const float* e4b)
{
    int t = blockIdx.x * blockDim.x + threadIdx.x;
    int stride = gridDim.x * blockDim.x;
    for (int i = t; i < 16*5;  i += stride) g_W1[i] = w1m[i] + softplusf(w1r[i]) * e1w[i];
    for (int i = t; i < 16;    i += stride) g_b1[i] = b1m[i] + softplusf(b1r[i]) * e1b[i];
    for (int i = t; i < 32*16; i += stride) g_W2[i] = w2m[i] + softplusf(w2r[i]) * e2w[i];
    for (int i = t; i < 32;    i += stride) g_b2[i] = b2m[i] + softplusf(b2r[i]) * e2b[i];
    for (int i = t; i < 16*35; i += stride) g_W3[i] = w3m[i] + softplusf(w3r[i]) * e3w[i];
    for (int i = t; i < 16;    i += stride) g_b3[i] = b3m[i] + softplusf(b3r[i]) * e3b[i];
    for (int i = t; i < 16;    i += stride) g_W4[i] = w4m[i] + softplusf(w4r[i]) * e4w[i];
    for (int i = t; i < 1;     i += stride) g_b4[i] = b4m[i] + softplusf(b4r[i]) * e4b[i];
}

// ---------------- helpers to read edge index in either width ----------------
__device__ __forceinline__ int load_src(const int* ei, int e) {
    int s = g_is_i32 ? ei[e] : ei[2*e];
    return ((unsigned)s >= NN) ? 0 : s;
}
__device__ __forceinline__ int load_dst(const int* ei, int e) {
    int d = g_is_i32 ? ei[NE + e] : ei[2*(NE + e)];
    return ((unsigned)d >= NN) ? 0 : d;
}

// ---------------- histogram ----------------
__global__ void hist_kernel(const int* __restrict__ ei)
{
    int e = blockIdx.x * blockDim.x + threadIdx.x;
    if (e < NE) atomicAdd(&g_cnt[load_dst(ei, e)], 1);
}

// ---------------- prep: x -> float4 ----------------
__global__ void prep_x(const float* __restrict__ x)
{
    int i = blockIdx.x * blockDim.x + threadIdx.x;
    if (i < NN) g_xp[i] = make_float4(x[3*i + 0], x[3*i + 1], x[3*i + 2], 0.f);
}

// ---------------- scan ----------------
__global__ void scan_blocks()
{
    __shared__ int s[SCAN_T];
    int t = threadIdx.x;
    int i = blockIdx.x * SCAN_T + t;
    int v = (i < NN) ? g_cnt[i] : 0;
    s[t] = v;
    __syncthreads();
    for (int off = 1; off < SCAN_T; off <<= 1) {
        int x = (t >= off) ? s[t - off] : 0;
        __syncthreads();
        s[t] += x;
        __syncthreads();
    }
    if (i < NN) g_off[i] = s[t] - v;
    if (t == SCAN_T - 1) g_bsum[blockIdx.x] = s[t];
}

__global__ void scan_sums()
{
    __shared__ int s[256];
    int t = threadIdx.x;
    int v = (t < SCAN_NB) ? g_bsum[t] : 0;
    s[t] = v;
    __syncthreads();
    for (int off = 1; off < 256; off <<= 1) {
        int x = (t >= off) ? s[t - off] : 0;
        __syncthreads();
        s[t] += x;
        __syncthreads();
    }
    if (t < SCAN_NB) g_bpre[t] = s[t] - v;
}

__global__ void scan_fixup()
{
    int i = blockIdx.x * blockDim.x + threadIdx.x;
    if (i < NN) g_pos[i] = g_off[i] + g_bpre[i / SCAN_T];
}

// ---------------- scatter (converts ea to half2 once) ----------------
__global__ void scatter_kernel(const int* __restrict__ ei, const float2* __restrict__ ea)
{
    int e = blockIdx.x * blockDim.x + threadIdx.x;
    if (e >= NE) return;
    int d = load_dst(ei, e);
    int p = atomicAdd(&g_pos[d], 1);
    float2 a = ea[e];
    __half2 ah = __floats2half2_rn(a.x, a.y);
    g_sedge[p] = make_int4(load_src(ei, e), d, (int)*reinterpret_cast<unsigned*>(&ah), 0);
}

// ---------------- fused edge MLP (fp16, strided EPT=4, two output phases) ----------------
__global__ void __launch_bounds__(EBLK) edge_fused_kernel()
{
    __shared__ unsigned sW1h[5*8];     // half2(W1[2j][i], W1[2j+1][i]) at [i*8+jp]
    __shared__ unsigned sb1h[8];
    __shared__ unsigned sW2h[16*16];   // half2(W2[2jp][k], W2[2jp+1][k]) at [k*16+jp]
    __shared__ unsigned sb2h[16];

    for (int i = threadIdx.x; i < 40; i += blockDim.x) {
        int in = i >> 3, jp = i & 7;
        __half2 h = __floats2half2_rn(g_W1[(2*jp)*5 + in], g_W1[(2*jp+1)*5 + in]);
        sW1h[i] = *reinterpret_cast<unsigned*>(&h);
    }
    for (int i = threadIdx.x; i < 8; i += blockDim.x) {
        __half2 h = __floats2half2_rn(g_b1[2*i], g_b1[2*i+1]);
        sb1h[i] = *reinterpret_cast<unsigned*>(&h);
    }
    for (int i = threadIdx.x; i < 256; i += blockDim.x) {
        int k = i >> 4, jp = i & 15;
        __half2 h = __floats2half2_rn(g_W2[(2*jp)*16 + k], g_W2[(2*jp+1)*16 + k]);
        sW2h[i] = *reinterpret_cast<unsigned*>(&h);
    }
    for (int i = threadIdx.x; i < 16; i += blockDim.x) {
        __half2 h = __floats2half2_rn(g_b2[2*i], g_b2[2*i+1]);
        sb2h[i] = *reinterpret_cast<unsigned*>(&h);
    }
    __syncthreads();

    const unsigned FULL = 0xffffffffu;
    int lane = threadIdx.x & 31;
    int block_base = blockIdx.x * EBLK * EPT;

    // load 4 strided edges (warp holds 32 consecutive sorted edges per window)
    int dst[EPT];
    unsigned m1[EPT][8];

    #pragma unroll
    for (int i = 0; i < EPT; i++) {
        int4 rec = g_sedge[block_base + i * EBLK + threadIdx.x];
        dst[i] = rec.y;
        float4 xv = g_xp[rec.x];

        __half2 i0 = __half2half2(__float2half(xv.x));
        __half2 i1 = __half2half2(__float2half(xv.y));
        __half2 i2 = __half2half2(__float2half(xv.z));
        unsigned eab = (unsigned)rec.z;
        __half2 eah = *reinterpret_cast<__half2*>(&eab);
        __half2 i3 = __low2half2(eah);
        __half2 i4 = __high2half2(eah);

        #pragma unroll
        for (int jp = 0; jp < 8; jp++) {
            __half2 a = *reinterpret_cast<__half2*>(&sb1h[jp]);
            a = __hfma2(*reinterpret_cast<__half2*>(&sW1h[0*8 + jp]), i0, a);
            a = __hfma2(*reinterpret_cast<__half2*>(&sW1h[1*8 + jp]), i1, a);
            a = __hfma2(*reinterpret_cast<__half2*>(&sW1h[2*8 + jp]), i2, a);
            a = __hfma2(*reinterpret_cast<__half2*>(&sW1h[3*8 + jp]), i3, a);
            a = __hfma2(*reinterpret_cast<__half2*>(&sW1h[4*8 + jp]), i4, a);
            m1[i][jp] = hmax2_bits(*reinterpret_cast<unsigned*>(&a), 0u);
        }
    }

    // two phases over output halves: jp 0..7 (agg cols 0..15), jp 8..15 (cols 16..31)
    #pragma unroll
    for (int ph = 0; ph < 2; ph++) {
        unsigned acc[EPT][8];
        #pragma unroll
        for (int i = 0; i < EPT; i++)
            #pragma unroll
            for (int jp = 0; jp < 8; jp++) acc[i][jp] = sb2h[ph*8 + jp];

        #pragma unroll
        for (int kp = 0; kp < 8; kp++) {
            __half2 lo[EPT], hi[EPT];
            #pragma unroll
            for (int i = 0; i < EPT; i++) {
                __half2 mk = *reinterpret_cast<__half2*>(&m1[i][kp]);
                lo[i] = __low2half2(mk);
                hi[i] = __high2half2(mk);
            }
            #pragma unroll
            for (int jp = 0; jp < 8; jp++) {
                __half2 w0 = *reinterpret_cast<__half2*>(&sW2h[(2*kp)*16   + ph*8 + jp]);
                __half2 w1 = *reinterpret_cast<__half2*>(&sW2h[(2*kp+1)*16 + ph*8 + jp]);
                #pragma unroll
                for (int i = 0; i < EPT; i++) {
                    __half2 a = *reinterpret_cast<__half2*>(&acc[i][jp]);
                    a = __hfma2(w0, lo[i], a);
                    a = __hfma2(w1, hi[i], a);
                    acc[i][jp] = *reinterpret_cast<unsigned*>(&a);
                }
            }
        }
        #pragma unroll
        for (int i = 0; i < EPT; i++)
            #pragma unroll
            for (int jp = 0; jp < 8; jp++) acc[i][jp] = hmax2_bits(acc[i][jp], 0u);

        // per-window segmented suffix max + head flush
        #pragma unroll
        for (int i = 0; i < EPT; i++) {
            int key = dst[i];
            #pragma unroll
            for (int s2 = 1; s2 < 32; s2 <<= 1) {
                int kn = __shfl_down_sync(FULL, key, s2);
                bool take = (lane + s2 < 32) && (kn == key);
                #pragma unroll
                for (int q = 0; q < 8; q++) {
                    unsigned o = __shfl_down_sync(FULL, acc[i][q], s2);
                    if (take) acc[i][q] = hmax2_bits(acc[i][q], o);
                }
            }
            int prev = __shfl_up_sync(FULL, key, 1);
            bool head = (lane == 0) || (prev != key);
            if (head) {
                unsigned* basep = &g_agg[(unsigned)key * 32u + ph * 16];
                #pragma unroll
                for (int q = 0; q < 8; q++) {
                    float2 f = __half22float2(*reinterpret_cast<__half2*>(&acc[i][q]));
                    unsigned b0 = __float_as_uint(f.x);
                    unsigned b1 = __float_as_uint(f.y);
                    if (b0) atomicMax(&basep[2*q],     b0);
                    if (b1) atomicMax(&basep[2*q + 1], b1);
                }
            }
        }
    }
}

// ---------------- node MLP (re-zeros agg in-place for next iteration) ----------------
__global__ void __launch_bounds__(256) node_kernel(float* __restrict__ out, int last)
{
    __shared__ float sW3[16*35], sb3[16], sW4[16], sb4[1];
    for (int i = threadIdx.x; i < 16*35; i += blockDim.x) sW3[i] = g_W3[i];
    for (int i = threadIdx.x; i < 16;    i += blockDim.x) sb3[i] = g_b3[i];
    for (int i = threadIdx.x; i < 16;    i += blockDim.x) sW4[i] = g_W4[i];
    if (threadIdx.x == 0) sb4[0] = g_b4[0];
    __syncthreads();

    int i = blockIdx.x * blockDim.x + threadIdx.x;
    if (i >= NN) return;

    float4 xv = g_xp[i];
    float h[35];
    h[0] = xv.x; h[1] = xv.y; h[2] = xv.z;

    uint4* ar = reinterpret_cast<uint4*>(&g_agg[(size_t)i * 32]);
    #pragma unroll
    for (int q = 0; q < 8; q++) {
        uint4 v = ar[q];
        h[3 + 4*q + 0] = __uint_as_float(v.x);
        h[3 + 4*q + 1] = __uint_as_float(v.y);
        h[3 + 4*q + 2] = __uint_as_float(v.z);
        h[3 + 4*q + 3] = __uint_as_float(v.w);
    }
    // re-zero agg while lines are hot
    #pragma unroll
    for (int q = 0; q < 8; q++) ar[q] = make_uint4(0u, 0u, 0u, 0u);

    float t[16];
    #pragma unroll
    for (int j = 0; j < 16; j++) {
        float s = sb3[j];
        #pragma unroll
        for (int k = 0; k < 35; k++) s = fmaf(sW3[j*35 + k], h[k], s);
        t[j] = fmaxf(s, 0.f);
    }

    float z = sb4[0];
    #pragma unroll
    for (int k = 0; k < 16; k++) z = fmaf(sW4[k], t[k], z);

    float comb = 1.f / (1.f + expf(-z));
    reinterpret_cast<float*>(&g_xp[i])[2] = comb;

    if (last) {
        out[3*i + 0] = xv.x;
        out[3*i + 1] = xv.y;
        out[3*i + 2] = comb;
    }
}

// ---------------- launch ----------------
extern "C" void kernel_launch(void* const* d_in, const int* in_sizes, int n_in,
                              void* d_out, int out_size)
{
    const float* x  = (const float*)d_in[0];
    const float* ea = (const float*)d_in[1];
    const void*  ei = d_in[2];
    const float* P[24];
    for (int i = 0; i < 24; i++) P[i] = (const float*)d_in[3 + i];

    zero_cnt<<<(NN + 255) / 256, 256>>>();              // also resets g_is_i32
    detect_layout<<<2, 256>>>((const unsigned*)ei);

    prep_weights<<<4, 256>>>(
        P[0],  P[1],  P[2],  P[3],  P[4],  P[5],
        P[6],  P[7],  P[8],  P[9],  P[10], P[11],
        P[12], P[13], P[14], P[15], P[16], P[17],
        P[18], P[19], P[20], P[21], P[22], P[23]);

    zero_agg<<<((NN * 32) / 4 + 255) / 256, 256>>>();   // seed; node_kernel re-zeros thereafter
    prep_x<<<(NN + 255) / 256, 256>>>(x);

    hist_kernel<<<(NE + 255) / 256, 256>>>((const int*)ei);
    scan_blocks<<<SCAN_NB, SCAN_T>>>();
    scan_sums<<<1, 256>>>();
    scan_fixup<<<(NN + 255) / 256, 256>>>();
    scatter_kernel<<<(NE + 255) / 256, 256>>>((const int*)ei, (const float2*)ea);

    const int edge_blocks = NE / (EBLK * EPT);      // 6250
    const int node_blocks = (NN + 255) / 256;       // 391

    for (int it = 0; it < 3; it++) {
        edge_fused_kernel<<<edge_blocks, EBLK>>>();
        node_kernel<<<node_blocks, 256>>>((float*)d_out, it == 2 ? 1 : 0);
    }
}

// round 14
// speedup vs baseline: 1.0317x; 1.0084x over previous
#include <cuda_runtime.h>
#include <cuda_fp16.h>
#include <math.h>

#define NE 3200000
#define NN 100000
#define EPT 4
#define EBLK 128
#define SCAN_T 512
#define SCAN_NB 196   // 196*512 = 100352 >= NN

// ---------------- device state ----------------
__device__ float g_W1[16*5];
__device__ float g_b1[16];
__device__ float g_W2[32*16];
__device__ float g_b2[32];
__device__ float g_W3[16*35];
__device__ float g_b3[16];
__device__ float g_W4[16];
__device__ float g_b4[1];

__device__ int4   g_sedge[NE];      // dst-sorted {src, dst, ea half2 bits, unused}
__device__ int    g_cnt[NN];
__device__ int    g_off[NN];
__device__ int    g_pos[NN];
__device__ int    g_bsum[SCAN_NB];

__device__ float4   g_xp[NN];       // (x0, x1, x2, unused)
__device__ unsigned g_agg[NN * 32]; // fp32 bit patterns, all values >= 0
__device__ int      g_is_i32;

__device__ __forceinline__ float softplusf(float v) {
    return (v > 20.f) ? v : log1pf(expf(v));
}

__device__ __forceinline__ unsigned hmax2_bits(unsigned a, unsigned b) {
    __half2 ha = *reinterpret_cast<__half2*>(&a);
    __half2 hb = *reinterpret_cast<__half2*>(&b);
    __half2 r = __hmax2(ha, hb);
    return *reinterpret_cast<unsigned*>(&r);
}

// ---------------- zero cnt + reset detect flag ----------------
__global__ void zero_cnt()
{
    int i = blockIdx.x * blockDim.x + threadIdx.x;
    if (i < NN) g_cnt[i] = 0;
    if (i == 0) g_is_i32 = 0;
}

__global__ void detect_layout(const unsigned* __restrict__ ei_words)
{
    int t = blockIdx.x * blockDim.x + threadIdx.x;   // 512 samples
    if (ei_words[2*t + 1] != 0u) atomicExch(&g_is_i32, 1);
}

__global__ void zero_agg()
{
    int i = blockIdx.x * blockDim.x + threadIdx.x;   // NN*32/4 uint4s
    uint4* p = reinterpret_cast<uint4*>(g_agg);
    if (i < (NN * 32) / 4) p[i] = make_uint4(0u, 0u, 0u, 0u);
}

// ---------------- prep: sample Bayesian weights ----------------
__global__ void prep_weights(
    const float* w1m, const float* w1r, const float* b1m, const float* b1r, const float* e1w, const float* e1b,
    const float* w2m, const float* w2r, const float* b2m, const float* b2r, const float* e2w, const float* e2b,
    const float* w3m, const float* w3r, const float* b3m, const float* b3r, const float* e3w, const float* e3b,
    const float* w4m, const float* w4r, const float* b4m, const float* b4r, const float* e4w, const float* e4b)
{
    int t = blockIdx.x * blockDim.x + threadIdx.x;
    int stride = gridDim.x * blockDim.x;
    for (int i = t; i < 16*5;  i += stride) g_W1[i] = w1m[i] + softplusf(w1r[i]) * e1w[i];
    for (int i = t; i < 16;    i += stride) g_b1[i] = b1m[i] + softplusf(b1r[i]) * e1b[i];
    for (int i = t; i < 32*16; i += stride) g_W2[i] = w2m[i] + softplusf(w2r[i]) * e2w[i];
    for (int i = t; i < 32;    i += stride) g_b2[i] = b2m[i] + softplusf(b2r[i]) * e2b[i];
    for (int i = t; i < 16*35; i += stride) g_W3[i] = w3m[i] + softplusf(w3r[i]) * e3w[i];
    for (int i = t; i < 16;    i += stride) g_b3[i] = b3m[i] + softplusf(b3r[i]) * e3b[i];
    for (int i = t; i < 16;    i += stride) g_W4[i] = w4m[i] + softplusf(w4r[i]) * e4w[i];
    for (int i = t; i < 1;     i += stride) g_b4[i] = b4m[i] + softplusf(b4r[i]) * e4b[i];
}

// ---------------- helpers to read edge index in either width ----------------
__device__ __forceinline__ int load_src(const int* ei, int e) {
    int s = g_is_i32 ? ei[e] : ei[2*e];
    return ((unsigned)s >= NN) ? 0 : s;
}
__device__ __forceinline__ int load_dst(const int* ei, int e) {
    int d = g_is_i32 ? ei[NE + e] : ei[2*(NE + e)];
    return ((unsigned)d >= NN) ? 0 : d;
}

// ---------------- histogram: 4 edges/thread (MLP) ----------------
__global__ void hist_kernel(const int* __restrict__ ei)
{
    int base = blockIdx.x * blockDim.x * 4 + threadIdx.x;
    int d0 = load_dst(ei, base + 0 * 256);
    int d1 = load_dst(ei, base + 1 * 256);
    int d2 = load_dst(ei, base + 2 * 256);
    int d3 = load_dst(ei, base + 3 * 256);
    atomicAdd(&g_cnt[d0], 1);
    atomicAdd(&g_cnt[d1], 1);
    atomicAdd(&g_cnt[d2], 1);
    atomicAdd(&g_cnt[d3], 1);
}

// ---------------- prep: x -> float4 ----------------
__global__ void prep_x(const float* __restrict__ x)
{
    int i = blockIdx.x * blockDim.x + threadIdx.x;
    if (i < NN) g_xp[i] = make_float4(x[3*i + 0], x[3*i + 1], x[3*i + 2], 0.f);
}

// ---------------- scan ----------------
__global__ void scan_blocks()
{
    __shared__ int s[SCAN_T];
    int t = threadIdx.x;
    int i = blockIdx.x * SCAN_T + t;
    int v = (i < NN) ? g_cnt[i] : 0;
    s[t] = v;
    __syncthreads();
    for (int off = 1; off < SCAN_T; off <<= 1) {
        int x = (t >= off) ? s[t - off] : 0;
        __syncthreads();
        s[t] += x;
        __syncthreads();
    }
    if (i < NN) g_off[i] = s[t] - v;
    if (t == SCAN_T - 1) g_bsum[blockIdx.x] = s[t];
}

// fixup: each block redundantly scans the 196 block sums in smem, then applies
__global__ void scan_fixup()
{
    __shared__ int s[256];
    int t = threadIdx.x;
    int v = (t < SCAN_NB) ? g_bsum[t] : 0;
    s[t] = v;
    __syncthreads();
    for (int off = 1; off < 256; off <<= 1) {
        int x = (t >= off) ? s[t - off] : 0;
        __syncthreads();
        s[t] += x;
        __syncthreads();
    }
    // s[b] is inclusive sum; exclusive prefix for block b is s[b] - bsum[b]
    int i = blockIdx.x * blockDim.x + threadIdx.x;
    if (i < NN) {
        int b = i / SCAN_T;
        int pre = s[b] - g_bsum[b];
        g_pos[i] = g_off[i] + pre;
    }
}

// ---------------- scatter: 2 edges/thread (MLP); converts ea to half2 once ----------------
__global__ void scatter_kernel(const int* __restrict__ ei, const float2* __restrict__ ea)
{
    int base = blockIdx.x * blockDim.x * 2 + threadIdx.x;
    int e0 = base, e1 = base + 256;
    int d0 = load_dst(ei, e0);
    int d1 = load_dst(ei, e1);
    int s0 = load_src(ei, e0);
    int s1 = load_src(ei, e1);
    float2 a0 = ea[e0];
    float2 a1 = ea[e1];
    int p0 = atomicAdd(&g_pos[d0], 1);
    int p1 = atomicAdd(&g_pos[d1], 1);
    __half2 h0 = __floats2half2_rn(a0.x, a0.y);
    __half2 h1 = __floats2half2_rn(a1.x, a1.y);
    g_sedge[p0] = make_int4(s0, d0, (int)*reinterpret_cast<unsigned*>(&h0), 0);
    g_sedge[p1] = make_int4(s1, d1, (int)*reinterpret_cast<unsigned*>(&h1), 0);
}

// ---------------- fused edge MLP (fp16, strided EPT=4, two output phases) ----------------
__global__ void __launch_bounds__(EBLK) edge_fused_kernel()
{
    __shared__ unsigned sW1h[5*8];     // half2(W1[2j][i], W1[2j+1][i]) at [i*8+jp]
    __shared__ unsigned sb1h[8];
    __shared__ unsigned sW2h[16*16];   // half2(W2[2jp][k], W2[2jp+1][k]) at [k*16+jp]
    __shared__ unsigned sb2h[16];

    for (int i = threadIdx.x; i < 40; i += blockDim.x) {
        int in = i >> 3, jp = i & 7;
        __half2 h = __floats2half2_rn(g_W1[(2*jp)*5 + in], g_W1[(2*jp+1)*5 + in]);
        sW1h[i] = *reinterpret_cast<unsigned*>(&h);
    }
    for (int i = threadIdx.x; i < 8; i += blockDim.x) {
        __half2 h = __floats2half2_rn(g_b1[2*i], g_b1[2*i+1]);
        sb1h[i] = *reinterpret_cast<unsigned*>(&h);
    }
    for (int i = threadIdx.x; i < 256; i += blockDim.x) {
        int k = i >> 4, jp = i & 15;
        __half2 h = __floats2half2_rn(g_W2[(2*jp)*16 + k], g_W2[(2*jp+1)*16 + k]);
        sW2h[i] = *reinterpret_cast<unsigned*>(&h);
    }
    for (int i = threadIdx.x; i < 16; i += blockDim.x) {
        __half2 h = __floats2half2_rn(g_b2[2*i], g_b2[2*i+1]);
        sb2h[i] = *reinterpret_cast<unsigned*>(&h);
    }
    __syncthreads();

    const unsigned FULL = 0xffffffffu;
    int lane = threadIdx.x & 31;
    int block_base = blockIdx.x * EBLK * EPT;

    // load 4 strided edges (warp holds 32 consecutive sorted edges per window)
    int dst[EPT];
    unsigned m1[EPT][8];

    #pragma unroll
    for (int i = 0; i < EPT; i++) {
        int4 rec = g_sedge[block_base + i * EBLK + threadIdx.x];
        dst[i] = rec.y;
        float4 xv = g_xp[rec.x];

        __half2 i0 = __half2half2(__float2half(xv.x));
        __half2 i1 = __half2half2(__float2half(xv.y));
        __half2 i2 = __half2half2(__float2half(xv.z));
        unsigned eab = (unsigned)rec.z;
        __half2 eah = *reinterpret_cast<__half2*>(&eab);
        __half2 i3 = __low2half2(eah);
        __half2 i4 = __high2half2(eah);

        #pragma unroll
        for (int jp = 0; jp < 8; jp++) {
            __half2 a = *reinterpret_cast<__half2*>(&sb1h[jp]);
            a = __hfma2(*reinterpret_cast<__half2*>(&sW1h[0*8 + jp]), i0, a);
            a = __hfma2(*reinterpret_cast<__half2*>(&sW1h[1*8 + jp]), i1, a);
            a = __hfma2(*reinterpret_cast<__half2*>(&sW1h[2*8 + jp]), i2, a);
            a = __hfma2(*reinterpret_cast<__half2*>(&sW1h[3*8 + jp]), i3, a);
            a = __hfma2(*reinterpret_cast<__half2*>(&sW1h[4*8 + jp]), i4, a);
            m1[i][jp] = hmax2_bits(*reinterpret_cast<unsigned*>(&a), 0u);
        }
    }

    // two phases over output halves: jp 0..7 (agg cols 0..15), jp 8..15 (cols 16..31)
    #pragma unroll
    for (int ph = 0; ph < 2; ph++) {
        unsigned acc[EPT][8];
        #pragma unroll
        for (int i = 0; i < EPT; i++)
            #pragma unroll
            for (int jp = 0; jp < 8; jp++) acc[i][jp] = sb2h[ph*8 + jp];

        #pragma unroll
        for (int kp = 0; kp < 8; kp++) {
            __half2 lo[EPT], hi[EPT];
            #pragma unroll
            for (int i = 0; i < EPT; i++) {
                __half2 mk = *reinterpret_cast<__half2*>(&m1[i][kp]);
                lo[i] = __low2half2(mk);
                hi[i] = __high2half2(mk);
            }
            #pragma unroll
            for (int jp = 0; jp < 8; jp++) {
                __half2 w0 = *reinterpret_cast<__half2*>(&sW2h[(2*kp)*16   + ph*8 + jp]);
                __half2 w1 = *reinterpret_cast<__half2*>(&sW2h[(2*kp+1)*16 + ph*8 + jp]);
                #pragma unroll
                for (int i = 0; i < EPT; i++) {
                    __half2 a = *reinterpret_cast<__half2*>(&acc[i][jp]);
                    a = __hfma2(w0, lo[i], a);
                    a = __hfma2(w1, hi[i], a);
                    acc[i][jp] = *reinterpret_cast<unsigned*>(&a);
                }
            }
        }
        #pragma unroll
        for (int i = 0; i < EPT; i++)
            #pragma unroll
            for (int jp = 0; jp < 8; jp++) acc[i][jp] = hmax2_bits(acc[i][jp], 0u);

        // per-window segmented suffix max + head flush
        #pragma unroll
        for (int i = 0; i < EPT; i++) {
            int key = dst[i];
            #pragma unroll
            for (int s2 = 1; s2 < 32; s2 <<= 1) {
                int kn = __shfl_down_sync(FULL, key, s2);
                bool take = (lane + s2 < 32) && (kn == key);
                #pragma unroll
                for (int q = 0; q < 8; q++) {
                    unsigned o = __shfl_down_sync(FULL, acc[i][q], s2);
                    if (take) acc[i][q] = hmax2_bits(acc[i][q], o);
                }
            }
            int prev = __shfl_up_sync(FULL, key, 1);
            bool head = (lane == 0) || (prev != key);
            if (head) {
                unsigned* basep = &g_agg[(unsigned)key * 32u + ph * 16];
                #pragma unroll
                for (int q = 0; q < 8; q++) {
                    float2 f = __half22float2(*reinterpret_cast<__half2*>(&acc[i][q]));
                    unsigned b0 = __float_as_uint(f.x);
                    unsigned b1 = __float_as_uint(f.y);
                    if (b0) atomicMax(&basep[2*q],     b0);
                    if (b1) atomicMax(&basep[2*q + 1], b1);
                }
            }
        }
    }
}

// ---------------- node MLP (re-zeros agg in-place for next iteration) ----------------
__global__ void __launch_bounds__(256) node_kernel(float* __restrict__ out, int last)
{
    __shared__ float sW3[16*35], sb3[16], sW4[16], sb4[1];
    for (int i = threadIdx.x; i < 16*35; i += blockDim.x) sW3[i] = g_W3[i];
    for (int i = threadIdx.x; i < 16;    i += blockDim.x) sb3[i] = g_b3[i];
    for (int i = threadIdx.x; i < 16;    i += blockDim.x) sW4[i] = g_W4[i];
    if (threadIdx.x == 0) sb4[0] = g_b4[0];
    __syncthreads();

    int i = blockIdx.x * blockDim.x + threadIdx.x;
    if (i >= NN) return;

    float4 xv = g_xp[i];
    float h[35];
    h[0] = xv.x; h[1] = xv.y; h[2] = xv.z;

    uint4* ar = reinterpret_cast<uint4*>(&g_agg[(size_t)i * 32]);
    #pragma unroll
    for (int q = 0; q < 8; q++) {
        uint4 v = ar[q];
        h[3 + 4*q + 0] = __uint_as_float(v.x);
        h[3 + 4*q + 1] = __uint_as_float(v.y);
        h[3 + 4*q + 2] = __uint_as_float(v.z);
        h[3 + 4*q + 3] = __uint_as_float(v.w);
    }
    // re-zero agg while lines are hot
    #pragma unroll
    for (int q = 0; q < 8; q++) ar[q] = make_uint4(0u, 0u, 0u, 0u);

    float t[16];
    #pragma unroll
    for (int j = 0; j < 16; j++) {
        float s = sb3[j];
        #pragma unroll
        for (int k = 0; k < 35; k++) s = fmaf(sW3[j*35 + k], h[k], s);
        t[j] = fmaxf(s, 0.f);
    }

    float z = sb4[0];
    #pragma unroll
    for (int k = 0; k < 16; k++) z = fmaf(sW4[k], t[k], z);

    float comb = 1.f / (1.f + expf(-z));
    reinterpret_cast<float*>(&g_xp[i])[2] = comb;

    if (last) {
        out[3*i + 0] = xv.x;
        out[3*i + 1] = xv.y;
        out[3*i + 2] = comb;
    }
}

// ---------------- launch ----------------
extern "C" void kernel_launch(void* const* d_in, const int* in_sizes, int n_in,
                              void* d_out, int out_size)
{
    const float* x  = (const float*)d_in[0];
    const float* ea = (const float*)d_in[1];
    const void*  ei = d_in[2];
    const float* P[24];
    for (int i = 0; i < 24; i++) P[i] = (const float*)d_in[3 + i];

    zero_cnt<<<(NN + 255) / 256, 256>>>();              // also resets g_is_i32
    detect_layout<<<2, 256>>>((const unsigned*)ei);

    prep_weights<<<4, 256>>>(
        P[0],  P[1],  P[2],  P[3],  P[4],  P[5],
        P[6],  P[7],  P[8],  P[9],  P[10], P[11],
        P[12], P[13], P[14], P[15], P[16], P[17],
        P[18], P[19], P[20], P[21], P[22], P[23]);

    zero_agg<<<((NN * 32) / 4 + 255) / 256, 256>>>();   // seed; node_kernel re-zeros thereafter
    prep_x<<<(NN + 255) / 256, 256>>>(x);

    hist_kernel<<<NE / (256 * 4), 256>>>((const int*)ei);            // 3125 blocks
    scan_blocks<<<SCAN_NB, SCAN_T>>>();
    scan_fixup<<<(NN + 255) / 256, 256>>>();                         // folds scan_sums
    scatter_kernel<<<NE / (256 * 2), 256>>>((const int*)ei, (const float2*)ea);  // 6250 blocks

    const int edge_blocks = NE / (EBLK * EPT);      // 6250
    const int node_blocks = (NN + 255) / 256;       // 391

    for (int it = 0; it < 3; it++) {
        edge_fused_kernel<<<edge_blocks, EBLK>>>();
        node_kernel<<<node_blocks, 256>>>((float*)d_out, it == 2 ? 1 : 0);
    }
}

// round 15
// speedup vs baseline: 1.0318x; 1.0001x over previous
#include <cuda_runtime.h>
#include <cuda_fp16.h>
#include <math.h>

#define NE 3200000
#define NN 100000
#define EPT 4
#define EBLK 128
#define SCAN_T 512
#define SCAN_NB 196   // 196*512 = 100352 >= NN

// ---------------- device state ----------------
__device__ float g_W1[16*5];
__device__ float g_b1[16];
__device__ float g_W2[32*16];
__device__ float g_b2[32];
__device__ float g_W3[16*35];
__device__ float g_b3[16];
__device__ float g_W4[16];
__device__ float g_b4[1];

__device__ int4   g_sedge[NE];      // dst-sorted {src, dst, ea half2 bits, unused}
__device__ int    g_cnt[NN];
__device__ int    g_off[NN];
__device__ int    g_pos[NN];
__device__ int    g_bsum[SCAN_NB];

__device__ float4   g_xp[NN];       // (x0, x1, x2, unused)
__device__ unsigned g_agg[NN * 32]; // fp32 bit patterns, all values >= 0
__device__ int      g_is_i32;       // zero-init; monotonic, input-determined (never reset)

__device__ __forceinline__ float softplusf(float v) {
    return (v > 20.f) ? v : log1pf(expf(v));
}

__device__ __forceinline__ unsigned hmax2_bits(unsigned a, unsigned b) {
    __half2 ha = *reinterpret_cast<__half2*>(&a);
    __half2 hb = *reinterpret_cast<__half2*>(&b);
    __half2 r = __hmax2(ha, hb);
    return *reinterpret_cast<unsigned*>(&r);
}

// ---------------- init: detect + zero cnt/agg + pack x + sample weights ----------------
// grid MUST be 3125 x 256 = 800000 threads (exact cover of agg zeroing)
__global__ void __launch_bounds__(256) init_kernel(
    const float* __restrict__ x, const unsigned* __restrict__ ei_words,
    const float* w1m, const float* w1r, const float* b1m, const float* b1r, const float* e1w, const float* e1b,
    const float* w2m, const float* w2r, const float* b2m, const float* b2r, const float* e2w, const float* e2b,
    const float* w3m, const float* w3r, const float* b3m, const float* b3r, const float* e3w, const float* e3b,
    const float* w4m, const float* w4r, const float* b4m, const float* b4r, const float* e4w, const float* e4b)
{
    int i = blockIdx.x * blockDim.x + threadIdx.x;

    // layout detection: int64 -> odd words of first 512 records are all zero
    if (i < 512) {
        if (ei_words[2*i + 1] != 0u) atomicExch(&g_is_i32, 1);
    }

    // zero agg (exact cover: 800000 uint4)
    reinterpret_cast<uint4*>(g_agg)[i] = make_uint4(0u, 0u, 0u, 0u);

    // zero cnt + pack x
    if (i < NN) {
        g_cnt[i] = 0;
        g_xp[i] = make_float4(x[3*i + 0], x[3*i + 1], x[3*i + 2], 0.f);
    }

    // sample weights (tiny arrays; direct guards)
    if (i < 16*5)  g_W1[i] = w1m[i] + softplusf(w1r[i]) * e1w[i];
    if (i < 16)    g_b1[i] = b1m[i] + softplusf(b1r[i]) * e1b[i];
    if (i < 32*16) g_W2[i] = w2m[i] + softplusf(w2r[i]) * e2w[i];
    if (i < 32)    g_b2[i] = b2m[i] + softplusf(b2r[i]) * e2b[i];
    if (i < 16*35) g_W3[i] = w3m[i] + softplusf(w3r[i]) * e3w[i];
    if (i < 16)    g_b3[i] = b3m[i] + softplusf(b3r[i]) * e3b[i];
    if (i < 16)    g_W4[i] = w4m[i] + softplusf(w4r[i]) * e4w[i];
    if (i < 1)     g_b4[i] = b4m[i] + softplusf(b4r[i]) * e4b[i];
}

// ---------------- helpers to read edge index in either width ----------------
__device__ __forceinline__ int load_src(const int* ei, int e) {
    int s = g_is_i32 ? ei[e] : ei[2*e];
    return ((unsigned)s >= NN) ? 0 : s;
}
__device__ __forceinline__ int load_dst(const int* ei, int e) {
    int d = g_is_i32 ? ei[NE + e] : ei[2*(NE + e)];
    return ((unsigned)d >= NN) ? 0 : d;
}

// ---------------- histogram: 4 edges/thread (MLP) ----------------
__global__ void hist_kernel(const int* __restrict__ ei)
{
    int base = blockIdx.x * blockDim.x * 4 + threadIdx.x;
    int d0 = load_dst(ei, base + 0 * 256);
    int d1 = load_dst(ei, base + 1 * 256);
    int d2 = load_dst(ei, base + 2 * 256);
    int d3 = load_dst(ei, base + 3 * 256);
    atomicAdd(&g_cnt[d0], 1);
    atomicAdd(&g_cnt[d1], 1);
    atomicAdd(&g_cnt[d2], 1);
    atomicAdd(&g_cnt[d3], 1);
}

// ---------------- scan ----------------
__global__ void scan_blocks()
{
    __shared__ int s[SCAN_T];
    int t = threadIdx.x;
    int i = blockIdx.x * SCAN_T + t;
    int v = (i < NN) ? g_cnt[i] : 0;
    s[t] = v;
    __syncthreads();
    for (int off = 1; off < SCAN_T; off <<= 1) {
        int x = (t >= off) ? s[t - off] : 0;
        __syncthreads();
        s[t] += x;
        __syncthreads();
    }
    if (i < NN) g_off[i] = s[t] - v;
    if (t == SCAN_T - 1) g_bsum[blockIdx.x] = s[t];
}

// fixup: each block redundantly scans the 196 block sums in smem, then applies
__global__ void scan_fixup()
{
    __shared__ int s[256];
    int t = threadIdx.x;
    int v = (t < SCAN_NB) ? g_bsum[t] : 0;
    s[t] = v;
    __syncthreads();
    for (int off = 1; off < 256; off <<= 1) {
        int x = (t >= off) ? s[t - off] : 0;
        __syncthreads();
        s[t] += x;
        __syncthreads();
    }
    int i = blockIdx.x * blockDim.x + threadIdx.x;
    if (i < NN) {
        int b = i / SCAN_T;
        int pre = s[b] - g_bsum[b];   // exclusive prefix for block b
        g_pos[i] = g_off[i] + pre;
    }
}

// ---------------- scatter: 4 edges/thread (MLP); converts ea to half2 once ----------------
__global__ void scatter_kernel(const int* __restrict__ ei, const float2* __restrict__ ea)
{
    int base = blockIdx.x * blockDim.x * 4 + threadIdx.x;
    #pragma unroll
    for (int k = 0; k < 4; k++) {
        int e = base + k * 256;
        int d = load_dst(ei, e);
        int s = load_src(ei, e);
        float2 a = ea[e];
        int p = atomicAdd(&g_pos[d], 1);
        __half2 h = __floats2half2_rn(a.x, a.y);
        g_sedge[p] = make_int4(s, d, (int)*reinterpret_cast<unsigned*>(&h), 0);
    }
}

// ---------------- fused edge MLP (fp16, strided EPT=4, two output phases) ----------------
__global__ void __launch_bounds__(EBLK) edge_fused_kernel()
{
    __shared__ unsigned sW1h[5*8];     // half2(W1[2j][i], W1[2j+1][i]) at [i*8+jp]
    __shared__ unsigned sb1h[8];
    __shared__ unsigned sW2h[16*16];   // half2(W2[2jp][k], W2[2jp+1][k]) at [k*16+jp]
    __shared__ unsigned sb2h[16];

    for (int i = threadIdx.x; i < 40; i += blockDim.x) {
        int in = i >> 3, jp = i & 7;
        __half2 h = __floats2half2_rn(g_W1[(2*jp)*5 + in], g_W1[(2*jp+1)*5 + in]);
        sW1h[i] = *reinterpret_cast<unsigned*>(&h);
    }
    for (int i = threadIdx.x; i < 8; i += blockDim.x) {
        __half2 h = __floats2half2_rn(g_b1[2*i], g_b1[2*i+1]);
        sb1h[i] = *reinterpret_cast<unsigned*>(&h);
    }
    for (int i = threadIdx.x; i < 256; i += blockDim.x) {
        int k = i >> 4, jp = i & 15;
        __half2 h = __floats2half2_rn(g_W2[(2*jp)*16 + k], g_W2[(2*jp+1)*16 + k]);
        sW2h[i] = *reinterpret_cast<unsigned*>(&h);
    }
    for (int i = threadIdx.x; i < 16; i += blockDim.x) {
        __half2 h = __floats2half2_rn(g_b2[2*i], g_b2[2*i+1]);
        sb2h[i] = *reinterpret_cast<unsigned*>(&h);
    }
    __syncthreads();

    const unsigned FULL = 0xffffffffu;
    int lane = threadIdx.x & 31;
    int block_base = blockIdx.x * EBLK * EPT;

    // load 4 strided edges (warp holds 32 consecutive sorted edges per window)
    int dst[EPT];
    unsigned m1[EPT][8];

    #pragma unroll
    for (int i = 0; i < EPT; i++) {
        int4 rec = g_sedge[block_base + i * EBLK + threadIdx.x];
        dst[i] = rec.y;
        float4 xv = g_xp[rec.x];

        __half2 i0 = __half2half2(__float2half(xv.x));
        __half2 i1 = __half2half2(__float2half(xv.y));
        __half2 i2 = __half2half2(__float2half(xv.z));
        unsigned eab = (unsigned)rec.z;
        __half2 eah = *reinterpret_cast<__half2*>(&eab);
        __half2 i3 = __low2half2(eah);
        __half2 i4 = __high2half2(eah);

        #pragma unroll
        for (int jp = 0; jp < 8; jp++) {
            __half2 a = *reinterpret_cast<__half2*>(&sb1h[jp]);
            a = __hfma2(*reinterpret_cast<__half2*>(&sW1h[0*8 + jp]), i0, a);
            a = __hfma2(*reinterpret_cast<__half2*>(&sW1h[1*8 + jp]), i1, a);
            a = __hfma2(*reinterpret_cast<__half2*>(&sW1h[2*8 + jp]), i2, a);
            a = __hfma2(*reinterpret_cast<__half2*>(&sW1h[3*8 + jp]), i3, a);
            a = __hfma2(*reinterpret_cast<__half2*>(&sW1h[4*8 + jp]), i4, a);
            m1[i][jp] = hmax2_bits(*reinterpret_cast<unsigned*>(&a), 0u);
        }
    }

    // two phases over output halves: jp 0..7 (agg cols 0..15), jp 8..15 (cols 16..31)
    #pragma unroll
    for (int ph = 0; ph < 2; ph++) {
        unsigned acc[EPT][8];
        #pragma unroll
        for (int i = 0; i < EPT; i++)
            #pragma unroll
            for (int jp = 0; jp < 8; jp++) acc[i][jp] = sb2h[ph*8 + jp];

        #pragma unroll
        for (int kp = 0; kp < 8; kp++) {
            __half2 lo[EPT], hi[EPT];
            #pragma unroll
            for (int i = 0; i < EPT; i++) {
                __half2 mk = *reinterpret_cast<__half2*>(&m1[i][kp]);
                lo[i] = __low2half2(mk);
                hi[i] = __high2half2(mk);
            }
            #pragma unroll
            for (int jp = 0; jp < 8; jp++) {
                __half2 w0 = *reinterpret_cast<__half2*>(&sW2h[(2*kp)*16   + ph*8 + jp]);
                __half2 w1 = *reinterpret_cast<__half2*>(&sW2h[(2*kp+1)*16 + ph*8 + jp]);
                #pragma unroll
                for (int i = 0; i < EPT; i++) {
                    __half2 a = *reinterpret_cast<__half2*>(&acc[i][jp]);
                    a = __hfma2(w0, lo[i], a);
                    a = __hfma2(w1, hi[i], a);
                    acc[i][jp] = *reinterpret_cast<unsigned*>(&a);
                }
            }
        }
        #pragma unroll
        for (int i = 0; i < EPT; i++)
            #pragma unroll
            for (int jp = 0; jp < 8; jp++) acc[i][jp] = hmax2_bits(acc[i][jp], 0u);

        // per-window segmented suffix max + head flush
        #pragma unroll
        for (int i = 0; i < EPT; i++) {
            int key = dst[i];
            #pragma unroll
            for (int s2 = 1; s2 < 32; s2 <<= 1) {
                int kn = __shfl_down_sync(FULL, key, s2);
                bool take = (lane + s2 < 32) && (kn == key);
                #pragma unroll
                for (int q = 0; q < 8; q++) {
                    unsigned o = __shfl_down_sync(FULL, acc[i][q], s2);
                    if (take) acc[i][q] = hmax2_bits(acc[i][q], o);
                }
            }
            int prev = __shfl_up_sync(FULL, key, 1);
            bool head = (lane == 0) || (prev != key);
            if (head) {
                unsigned* basep = &g_agg[(unsigned)key * 32u + ph * 16];
                #pragma unroll
                for (int q = 0; q < 8; q++) {
                    float2 f = __half22float2(*reinterpret_cast<__half2*>(&acc[i][q]));
                    unsigned b0 = __float_as_uint(f.x);
                    unsigned b1 = __float_as_uint(f.y);
                    if (b0) atomicMax(&basep[2*q],     b0);
                    if (b1) atomicMax(&basep[2*q + 1], b1);
                }
            }
        }
    }
}

// ---------------- node MLP (re-zeros agg in-place for next iteration) ----------------
__global__ void __launch_bounds__(256) node_kernel(float* __restrict__ out, int last)
{
    __shared__ float sW3[16*35], sb3[16], sW4[16], sb4[1];
    for (int i = threadIdx.x; i < 16*35; i += blockDim.x) sW3[i] = g_W3[i];
    for (int i = threadIdx.x; i < 16;    i += blockDim.x) sb3[i] = g_b3[i];
    for (int i = threadIdx.x; i < 16;    i += blockDim.x) sW4[i] = g_W4[i];
    if (threadIdx.x == 0) sb4[0] = g_b4[0];
    __syncthreads();

    int i = blockIdx.x * blockDim.x + threadIdx.x;
    if (i >= NN) return;

    float4 xv = g_xp[i];
    float h[35];
    h[0] = xv.x; h[1] = xv.y; h[2] = xv.z;

    uint4* ar = reinterpret_cast<uint4*>(&g_agg[(size_t)i * 32]);
    #pragma unroll
    for (int q = 0; q < 8; q++) {
        uint4 v = ar[q];
        h[3 + 4*q + 0] = __uint_as_float(v.x);
        h[3 + 4*q + 1] = __uint_as_float(v.y);
        h[3 + 4*q + 2] = __uint_as_float(v.z);
        h[3 + 4*q + 3] = __uint_as_float(v.w);
    }
    // re-zero agg while lines are hot
    #pragma unroll
    for (int q = 0; q < 8; q++) ar[q] = make_uint4(0u, 0u, 0u, 0u);

    float t[16];
    #pragma unroll
    for (int j = 0; j < 16; j++) {
        float s = sb3[j];
        #pragma unroll
        for (int k = 0; k < 35; k++) s = fmaf(sW3[j*35 + k], h[k], s);
        t[j] = fmaxf(s, 0.f);
    }

    float z = sb4[0];
    #pragma unroll
    for (int k = 0; k < 16; k++) z = fmaf(sW4[k], t[k], z);

    float comb = 1.f / (1.f + expf(-z));
    reinterpret_cast<float*>(&g_xp[i])[2] = comb;

    if (last) {
        out[3*i + 0] = xv.x;
        out[3*i + 1] = xv.y;
        out[3*i + 2] = comb;
    }
}

// ---------------- launch ----------------
extern "C" void kernel_launch(void* const* d_in, const int* in_sizes, int n_in,
                              void* d_out, int out_size)
{
    const float* x  = (const float*)d_in[0];
    const float* ea = (const float*)d_in[1];
    const void*  ei = d_in[2];
    const float* P[24];
    for (int i = 0; i < 24; i++) P[i] = (const float*)d_in[3 + i];

    init_kernel<<<3125, 256>>>(x, (const unsigned*)ei,
        P[0],  P[1],  P[2],  P[3],  P[4],  P[5],
        P[6],  P[7],  P[8],  P[9],  P[10], P[11],
        P[12], P[13], P[14], P[15], P[16], P[17],
        P[18], P[19], P[20], P[21], P[22], P[23]);                   // #0

    hist_kernel<<<NE / (256 * 4), 256>>>((const int*)ei);            // #1
    scan_blocks<<<SCAN_NB, SCAN_T>>>();                              // #2
    scan_fixup<<<(NN + 255) / 256, 256>>>();                         // #3
    scatter_kernel<<<NE / (256 * 4), 256>>>((const int*)ei, (const float2*)ea);  // #4

    const int edge_blocks = NE / (EBLK * EPT);      // 6250
    const int node_blocks = (NN + 255) / 256;       // 391

    for (int it = 0; it < 3; it++) {
        edge_fused_kernel<<<edge_blocks, EBLK>>>();                  // #5, #7, #9
        node_kernel<<<node_blocks, 256>>>((float*)d_out, it == 2 ? 1 : 0);
    }
}

// round 16
// speedup vs baseline: 1.0419x; 1.0099x over previous
#include <cuda_runtime.h>
#include <cuda_fp16.h>
#include <math.h>

#define NE 3200000
#define NN 100000
#define EPT 4
#define EBLK 128
#define SCAN_T 512
#define SCAN_NB 196   // 196*512 = 100352 >= NN

// ---------------- device state ----------------
__device__ float g_W1[16*5];
__device__ float g_b1[16];
__device__ float g_W2[32*16];
__device__ float g_b2[32];
__device__ float g_W3[16*35];
__device__ float g_b3[16];
__device__ float g_W4[16];
__device__ float g_b4[1];

__device__ int4   g_sedge[NE];      // dst-sorted {src, dst, ea half2 bits, unused}
__device__ int    g_cnt[NN];
__device__ int    g_off[NN];
__device__ int    g_pos[NN];
__device__ int    g_bsum[SCAN_NB];

__device__ float4   g_xp[NN];       // fp32 (x0, x1, x2, unused) — node MLP + output path
__device__ uint2    g_xh[NN];       // half-packed {half2(x0,x1), half2(x2,0)} — edge gather
__device__ unsigned g_agg[NN * 32]; // fp32 bit patterns, all values >= 0
__device__ int      g_is_i32;       // zero-init; monotonic, input-determined (never reset)

__device__ __forceinline__ float softplusf(float v) {
    return (v > 20.f) ? v : log1pf(expf(v));
}

__device__ __forceinline__ unsigned hmax2_bits(unsigned a, unsigned b) {
    __half2 ha = *reinterpret_cast<__half2*>(&a);
    __half2 hb = *reinterpret_cast<__half2*>(&b);
    __half2 r = __hmax2(ha, hb);
    return *reinterpret_cast<unsigned*>(&r);
}

// ---------------- init: detect + zero cnt/agg + pack x (fp32 + half) + weights ----------------
// grid MUST be 3125 x 256 = 800000 threads (exact cover of agg zeroing)
__global__ void __launch_bounds__(256) init_kernel(
    const float* __restrict__ x, const unsigned* __restrict__ ei_words,
    const float* w1m, const float* w1r, const float* b1m, const float* b1r, const float* e1w, const float* e1b,
    const float* w2m, const float* w2r, const float* b2m, const float* b2r, const float* e2w, const float* e2b,
    const float* w3m, const float* w3r, const float* b3m, const float* b3r, const float* e3w, const float* e3b,
    const float* w4m, const float* w4r, const float* b4m, const float* b4r, const float* e4w, const float* e4b)
{
    int i = blockIdx.x * blockDim.x + threadIdx.x;

    // layout detection: int64 -> odd words of first 512 records are all zero
    if (i < 512) {
        if (ei_words[2*i + 1] != 0u) atomicExch(&g_is_i32, 1);
    }

    // zero agg (exact cover: 800000 uint4)
    reinterpret_cast<uint4*>(g_agg)[i] = make_uint4(0u, 0u, 0u, 0u);

    // zero cnt + pack x (both precisions)
    if (i < NN) {
        g_cnt[i] = 0;
        float x0 = x[3*i + 0], x1 = x[3*i + 1], x2 = x[3*i + 2];
        g_xp[i] = make_float4(x0, x1, x2, 0.f);
        __half2 h01 = __floats2half2_rn(x0, x1);
        __half2 h2  = __floats2half2_rn(x2, 0.f);
        g_xh[i] = make_uint2(*reinterpret_cast<unsigned*>(&h01),
                             *reinterpret_cast<unsigned*>(&h2));
    }

    // sample weights (tiny arrays; direct guards)
    if (i < 16*5)  g_W1[i] = w1m[i] + softplusf(w1r[i]) * e1w[i];
    if (i < 16)    g_b1[i] = b1m[i] + softplusf(b1r[i]) * e1b[i];
    if (i < 32*16) g_W2[i] = w2m[i] + softplusf(w2r[i]) * e2w[i];
    if (i < 32)    g_b2[i] = b2m[i] + softplusf(b2r[i]) * e2b[i];
    if (i < 16*35) g_W3[i] = w3m[i] + softplusf(w3r[i]) * e3w[i];
    if (i < 16)    g_b3[i] = b3m[i] + softplusf(b3r[i]) * e3b[i];
    if (i < 16)    g_W4[i] = w4m[i] + softplusf(w4r[i]) * e4w[i];
    if (i < 1)     g_b4[i] = b4m[i] + softplusf(b4r[i]) * e4b[i];
}

// ---------------- helpers to read edge index in either width ----------------
__device__ __forceinline__ int load_src(const int* ei, int e) {
    int s = g_is_i32 ? ei[e] : ei[2*e];
    return ((unsigned)s >= NN) ? 0 : s;
}
__device__ __forceinline__ int load_dst(const int* ei, int e) {
    int d = g_is_i32 ? ei[NE + e] : ei[2*(NE + e)];
    return ((unsigned)d >= NN) ? 0 : d;
}

// ---------------- histogram: 4 edges/thread (MLP) ----------------
__global__ void hist_kernel(const int* __restrict__ ei)
{
    int base = blockIdx.x * blockDim.x * 4 + threadIdx.x;
    int d0 = load_dst(ei, base + 0 * 256);
    int d1 = load_dst(ei, base + 1 * 256);
    int d2 = load_dst(ei, base + 2 * 256);
    int d3 = load_dst(ei, base + 3 * 256);
    atomicAdd(&g_cnt[d0], 1);
    atomicAdd(&g_cnt[d1], 1);
    atomicAdd(&g_cnt[d2], 1);
    atomicAdd(&g_cnt[d3], 1);
}

// ---------------- scan ----------------
__global__ void scan_blocks()
{
    __shared__ int s[SCAN_T];
    int t = threadIdx.x;
    int i = blockIdx.x * SCAN_T + t;
    int v = (i < NN) ? g_cnt[i] : 0;
    s[t] = v;
    __syncthreads();
    for (int off = 1; off < SCAN_T; off <<= 1) {
        int x = (t >= off) ? s[t - off] : 0;
        __syncthreads();
        s[t] += x;
        __syncthreads();
    }
    if (i < NN) g_off[i] = s[t] - v;
    if (t == SCAN_T - 1) g_bsum[blockIdx.x] = s[t];
}

// fixup: each block redundantly scans the 196 block sums in smem, then applies
__global__ void scan_fixup()
{
    __shared__ int s[256];
    int t = threadIdx.x;
    int v = (t < SCAN_NB) ? g_bsum[t] : 0;
    s[t] = v;
    __syncthreads();
    for (int off = 1; off < 256; off <<= 1) {
        int x = (t >= off) ? s[t - off] : 0;
        __syncthreads();
        s[t] += x;
        __syncthreads();
    }
    int i = blockIdx.x * blockDim.x + threadIdx.x;
    if (i < NN) {
        int b = i / SCAN_T;
        int pre = s[b] - g_bsum[b];   // exclusive prefix for block b
        g_pos[i] = g_off[i] + pre;
    }
}

// ---------------- scatter: 4 edges/thread (MLP); converts ea to half2 once ----------------
__global__ void scatter_kernel(const int* __restrict__ ei, const float2* __restrict__ ea)
{
    int base = blockIdx.x * blockDim.x * 4 + threadIdx.x;
    #pragma unroll
    for (int k = 0; k < 4; k++) {
        int e = base + k * 256;
        int d = load_dst(ei, e);
        int s = load_src(ei, e);
        float2 a = ea[e];
        int p = atomicAdd(&g_pos[d], 1);
        __half2 h = __floats2half2_rn(a.x, a.y);
        g_sedge[p] = make_int4(s, d, (int)*reinterpret_cast<unsigned*>(&h), 0);
    }
}

// ---------------- fused edge MLP (fp16, strided EPT=4, two output phases) ----------------
__global__ void __launch_bounds__(EBLK) edge_fused_kernel()
{
    __shared__ unsigned sW1h[5*8];     // half2(W1[2j][i], W1[2j+1][i]) at [i*8+jp]
    __shared__ unsigned sb1h[8];
    __shared__ unsigned sW2h[16*16];   // half2(W2[2jp][k], W2[2jp+1][k]) at [k*16+jp]
    __shared__ unsigned sb2h[16];

    for (int i = threadIdx.x; i < 40; i += blockDim.x) {
        int in = i >> 3, jp = i & 7;
        __half2 h = __floats2half2_rn(g_W1[(2*jp)*5 + in], g_W1[(2*jp+1)*5 + in]);
        sW1h[i] = *reinterpret_cast<unsigned*>(&h);
    }
    for (int i = threadIdx.x; i < 8; i += blockDim.x) {
        __half2 h = __floats2half2_rn(g_b1[2*i], g_b1[2*i+1]);
        sb1h[i] = *reinterpret_cast<unsigned*>(&h);
    }
    for (int i = threadIdx.x; i < 256; i += blockDim.x) {
        int k = i >> 4, jp = i & 15;
        __half2 h = __floats2half2_rn(g_W2[(2*jp)*16 + k], g_W2[(2*jp+1)*16 + k]);
        sW2h[i] = *reinterpret_cast<unsigned*>(&h);
    }
    for (int i = threadIdx.x; i < 16; i += blockDim.x) {
        __half2 h = __floats2half2_rn(g_b2[2*i], g_b2[2*i+1]);
        sb2h[i] = *reinterpret_cast<unsigned*>(&h);
    }
    __syncthreads();

    const unsigned FULL = 0xffffffffu;
    int lane = threadIdx.x & 31;
    int block_base = blockIdx.x * EBLK * EPT;

    // load 4 strided edges (warp holds 32 consecutive sorted edges per window)
    int dst[EPT];
    unsigned m1[EPT][8];

    #pragma unroll
    for (int i = 0; i < EPT; i++) {
        int4 rec = g_sedge[block_base + i * EBLK + threadIdx.x];
        dst[i] = rec.y;
        uint2 xh = g_xh[rec.x];                   // 8B half-packed gather

        __half2 x01 = *reinterpret_cast<__half2*>(&xh.x);
        __half2 x2p = *reinterpret_cast<__half2*>(&xh.y);
        __half2 i0 = __low2half2(x01);
        __half2 i1 = __high2half2(x01);
        __half2 i2 = __low2half2(x2p);
        unsigned eab = (unsigned)rec.z;
        __half2 eah = *reinterpret_cast<__half2*>(&eab);
        __half2 i3 = __low2half2(eah);
        __half2 i4 = __high2half2(eah);

        #pragma unroll
        for (int jp = 0; jp < 8; jp++) {
            __half2 a = *reinterpret_cast<__half2*>(&sb1h[jp]);
            a = __hfma2(*reinterpret_cast<__half2*>(&sW1h[0*8 + jp]), i0, a);
            a = __hfma2(*reinterpret_cast<__half2*>(&sW1h[1*8 + jp]), i1, a);
            a = __hfma2(*reinterpret_cast<__half2*>(&sW1h[2*8 + jp]), i2, a);
            a = __hfma2(*reinterpret_cast<__half2*>(&sW1h[3*8 + jp]), i3, a);
            a = __hfma2(*reinterpret_cast<__half2*>(&sW1h[4*8 + jp]), i4, a);
            m1[i][jp] = hmax2_bits(*reinterpret_cast<unsigned*>(&a), 0u);
        }
    }

    // two phases over output halves: jp 0..7 (agg cols 0..15), jp 8..15 (cols 16..31)
    #pragma unroll
    for (int ph = 0; ph < 2; ph++) {
        unsigned acc[EPT][8];
        #pragma unroll
        for (int i = 0; i < EPT; i++)
            #pragma unroll
            for (int jp = 0; jp < 8; jp++) acc[i][jp] = sb2h[ph*8 + jp];

        #pragma unroll
        for (int kp = 0; kp < 8; kp++) {
            __half2 lo[EPT], hi[EPT];
            #pragma unroll
            for (int i = 0; i < EPT; i++) {
                __half2 mk = *reinterpret_cast<__half2*>(&m1[i][kp]);
                lo[i] = __low2half2(mk);
                hi[i] = __high2half2(mk);
            }
            #pragma unroll
            for (int jp = 0; jp < 8; jp++) {
                __half2 w0 = *reinterpret_cast<__half2*>(&sW2h[(2*kp)*16   + ph*8 + jp]);
                __half2 w1 = *reinterpret_cast<__half2*>(&sW2h[(2*kp+1)*16 + ph*8 + jp]);
                #pragma unroll
                for (int i = 0; i < EPT; i++) {
                    __half2 a = *reinterpret_cast<__half2*>(&acc[i][jp]);
                    a = __hfma2(w0, lo[i], a);
                    a = __hfma2(w1, hi[i], a);
                    acc[i][jp] = *reinterpret_cast<unsigned*>(&a);
                }
            }
        }
        #pragma unroll
        for (int i = 0; i < EPT; i++)
            #pragma unroll
            for (int jp = 0; jp < 8; jp++) acc[i][jp] = hmax2_bits(acc[i][jp], 0u);

        // per-window segmented suffix max + head flush
        #pragma unroll
        for (int i = 0; i < EPT; i++) {
            int key = dst[i];
            #pragma unroll
            for (int s2 = 1; s2 < 32; s2 <<= 1) {
                int kn = __shfl_down_sync(FULL, key, s2);
                bool take = (lane + s2 < 32) && (kn == key);
                #pragma unroll
                for (int q = 0; q < 8; q++) {
                    unsigned o = __shfl_down_sync(FULL, acc[i][q], s2);
                    if (take) acc[i][q] = hmax2_bits(acc[i][q], o);
                }
            }
            int prev = __shfl_up_sync(FULL, key, 1);
            bool head = (lane == 0) || (prev != key);
            if (head) {
                unsigned* basep = &g_agg[(unsigned)key * 32u + ph * 16];
                #pragma unroll
                for (int q = 0; q < 8; q++) {
                    float2 f = __half22float2(*reinterpret_cast<__half2*>(&acc[i][q]));
                    unsigned b0 = __float_as_uint(f.x);
                    unsigned b1 = __float_as_uint(f.y);
                    if (b0) atomicMax(&basep[2*q],     b0);
                    if (b1) atomicMax(&basep[2*q + 1], b1);
                }
            }
        }
    }
}

// ---------------- node MLP (re-zeros agg; refreshes both x tables) ----------------
__global__ void __launch_bounds__(256) node_kernel(float* __restrict__ out, int last)
{
    __shared__ float sW3[16*35], sb3[16], sW4[16], sb4[1];
    for (int i = threadIdx.x; i < 16*35; i += blockDim.x) sW3[i] = g_W3[i];
    for (int i = threadIdx.x; i < 16;    i += blockDim.x) sb3[i] = g_b3[i];
    for (int i = threadIdx.x; i < 16;    i += blockDim.x) sW4[i] = g_W4[i];
    if (threadIdx.x == 0) sb4[0] = g_b4[0];
    __syncthreads();

    int i = blockIdx.x * blockDim.x + threadIdx.x;
    if (i >= NN) return;

    float4 xv = g_xp[i];
    float h[35];
    h[0] = xv.x; h[1] = xv.y; h[2] = xv.z;

    uint4* ar = reinterpret_cast<uint4*>(&g_agg[(size_t)i * 32]);
    #pragma unroll
    for (int q = 0; q < 8; q++) {
        uint4 v = ar[q];
        h[3 + 4*q + 0] = __uint_as_float(v.x);
        h[3 + 4*q + 1] = __uint_as_float(v.y);
        h[3 + 4*q + 2] = __uint_as_float(v.z);
        h[3 + 4*q + 3] = __uint_as_float(v.w);
    }
    // re-zero agg while lines are hot
    #pragma unroll
    for (int q = 0; q < 8; q++) ar[q] = make_uint4(0u, 0u, 0u, 0u);

    float t[16];
    #pragma unroll
    for (int j = 0; j < 16; j++) {
        float s = sb3[j];
        #pragma unroll
        for (int k = 0; k < 35; k++) s = fmaf(sW3[j*35 + k], h[k], s);
        t[j] = fmaxf(s, 0.f);
    }

    float z = sb4[0];
    #pragma unroll
    for (int k = 0; k < 16; k++) z = fmaf(sW4[k], t[k], z);

    float comb = 1.f / (1.f + expf(-z));
    reinterpret_cast<float*>(&g_xp[i])[2] = comb;     // fp32 table (node/output path)
    {
        __half2 h01 = __floats2half2_rn(xv.x, xv.y);  // half table (edge gather path)
        __half2 h2  = __floats2half2_rn(comb, 0.f);
        g_xh[i] = make_uint2(*reinterpret_cast<unsigned*>(&h01),
                             *reinterpret_cast<unsigned*>(&h2));
    }

    if (last) {
        out[3*i + 0] = xv.x;
        out[3*i + 1] = xv.y;
        out[3*i + 2] = comb;
    }
}

// ---------------- launch ----------------
extern "C" void kernel_launch(void* const* d_in, const int* in_sizes, int n_in,
                              void* d_out, int out_size)
{
    const float* x  = (const float*)d_in[0];
    const float* ea = (const float*)d_in[1];
    const void*  ei = d_in[2];
    const float* P[24];
    for (int i = 0; i < 24; i++) P[i] = (const float*)d_in[3 + i];

    init_kernel<<<3125, 256>>>(x, (const unsigned*)ei,
        P[0],  P[1],  P[2],  P[3],  P[4],  P[5],
        P[6],  P[7],  P[8],  P[9],  P[10], P[11],
        P[12], P[13], P[14], P[15], P[16], P[17],
        P[18], P[19], P[20], P[21], P[22], P[23]);

    hist_kernel<<<NE / (256 * 4), 256>>>((const int*)ei);
    scan_blocks<<<SCAN_NB, SCAN_T>>>();
    scan_fixup<<<(NN + 255) / 256, 256>>>();
    scatter_kernel<<<NE / (256 * 4), 256>>>((const int*)ei, (const float2*)ea);

    const int edge_blocks = NE / (EBLK * EPT);      // 6250
    const int node_blocks = (NN + 255) / 256;       // 391

    for (int it = 0; it < 3; it++) {
        edge_fused_kernel<<<edge_blocks, EBLK>>>();
        node_kernel<<<node_blocks, 256>>>((float*)d_out, it == 2 ? 1 : 0);
    }
}